// round 14
// baseline (speedup 1.0000x reference)
#include <cuda_runtime.h>
#include <cuda_fp16.h>
#include <math.h>

#define NMAX 50000
#define EMAX 800000
#define C 256

typedef unsigned long long u64;
typedef unsigned int u32;

// ---------------- scratch (static device globals; no allocation) ----------------
// g_cnt / g_scanstate are zero-initialized at load and re-zeroed by final_kernel.
__device__ int   g_cnt[NMAX];
__device__ u32   g_scanstate[64];
__device__ int   g_rowstart[NMAX + 1];
__device__ int   g_cursor[NMAX];
__device__ int   g_csr[EMAX];
__device__ __align__(16) float g_pq[NMAX * 4];
__device__ __align__(16) __half g_Whalf[256 * 512];        // [W1l|W1r] fp16
__device__ __align__(16) float4 g_W2pack[256];             // {W2l0,W2l1,W2r0,W2r1}[col]
__device__ __align__(16) __half g_agghalf[(size_t)NMAX * C];
__device__ __align__(16) __half g_xhalf[(size_t)NMAX * C];

__device__ __forceinline__ u32 packhf(float a, float b) {
    __half2 h = __floats2half2_rn(a, b);
    return *(u32*)&h;
}
__device__ __forceinline__ void mma16816(float* d, const u32* a, const u32* b) {
    asm volatile(
        "mma.sync.aligned.m16n8k16.row.col.f32.f16.f16.f32 "
        "{%0,%1,%2,%3}, {%4,%5,%6,%7}, {%8,%9}, {%0,%1,%2,%3};"
        : "+f"(d[0]), "+f"(d[1]), "+f"(d[2]), "+f"(d[3])
        : "r"(a[0]), "r"(a[1]), "r"(a[2]), "r"(a[3]), "r"(b[0]), "r"(b[1]));
}
__device__ __forceinline__ void ldsm_x4(u32& r0, u32& r1, u32& r2, u32& r3, u32 addr) {
    asm volatile("ldmatrix.sync.aligned.m8n8.x4.shared.b16 {%0,%1,%2,%3}, [%4];"
                 : "=r"(r0), "=r"(r1), "=r"(r2), "=r"(r3) : "r"(addr));
}
__device__ __forceinline__ u32 smem_u32(const void* p) {
    u32 a;
    asm("{ .reg .u64 t; cvta.to.shared.u64 t, %1; cvt.u32.u64 %0, t; }" : "=r"(a) : "l"(p));
    return a;
}
#define CP16(dst, src, sz) \
    asm volatile("cp.async.cg.shared.global [%0], [%1], 16, %2;" \
                 :: "r"(dst), "l"(src), "r"(sz))
#define CP_COMMIT() asm volatile("cp.async.commit_group;")
#define CP_WAIT(n)  asm volatile("cp.async.wait_group %0;" :: "n"(n))

// ---------------- merged prep: x->fp16 | edge count (inline dtype) | W->fp16 ----------
__global__ void prep_kernel(const float* __restrict__ x, const int* __restrict__ ei,
                            const float* __restrict__ W1l, const float* __restrict__ W1r,
                            const float* __restrict__ W2l, const float* __restrict__ W2r,
                            int n, int E, int nbx, int nbc) {
    int b = blockIdx.x;
    int tid = threadIdx.x;
    if (b < nbx) {
        int idx = b * 256 + tid;
        if (idx < n * 64) {
            float4 v = *(const float4*)(x + (size_t)idx * 4);
            *(uint2*)(g_xhalf + (size_t)idx * 4) =
                make_uint2(packhf(v.x, v.y), packhf(v.z, v.w));
        }
    } else if (b < nbx + nbc) {
        __shared__ int s_nz;
        if (tid == 0) s_nz = 0;
        __syncthreads();
        if (((const unsigned*)ei)[2 * tid + 1] != 0u) atomicAdd(&s_nz, 1);
        __syncthreads();
        bool is64 = (s_nz == 0);
        int e = (b - nbx) * 256 + tid;
        if (e < E) {
            int d;
            if (is64) d = (int)((const long long*)ei)[(size_t)E + e];
            else      d = ei[E + e];
            if ((unsigned)d >= (unsigned)n) d = 0;
            atomicAdd(&g_cnt[d], 1);
        }
    } else {
        int idx = (b - nbx - nbc) * 256 + tid;   // < 131072
        int nrow = idx >> 9;
        int k = idx & 511;
        float w = (k < 256) ? W1l[nrow * 256 + k] : W1r[nrow * 256 + (k - 256)];
        g_Whalf[idx] = __float2half_rn(w);
        if (idx < 256)
            g_W2pack[idx] = make_float4(W2l[idx], W2l[256 + idx], W2r[idx], W2r[256 + idx]);
    }
}

// ---------------- single-kernel exclusive scan (decoupled lookback, nb<=49 blocks) ----
#define FLAG_AGG 0x40000000u
#define FLAG_INC 0x80000000u
#define VALMASK  0x0FFFFFFFu

__global__ void scan_kernel(int n, int nb) {
    int b = blockIdx.x;
    int i = b * 1024 + threadIdx.x;
    int v = (i < n) ? g_cnt[i] : 0;
    int lane = threadIdx.x & 31, wid = threadIdx.x >> 5;
    int x = v;
    #pragma unroll
    for (int off = 1; off < 32; off <<= 1) {
        int t = __shfl_up_sync(0xffffffffu, x, off);
        if (lane >= off) x += t;
    }
    __shared__ int wsum[32];
    __shared__ int s_prefix, s_total;
    if (lane == 31) wsum[wid] = x;
    __syncthreads();
    if (wid == 0) {
        int s = wsum[lane];
        #pragma unroll
        for (int off = 1; off < 32; off <<= 1) {
            int t = __shfl_up_sync(0xffffffffu, s, off);
            if (lane >= off) s += t;
        }
        wsum[lane] = s;
        if (lane == 31) s_total = s;
    }
    __syncthreads();
    int incl = x + (wid > 0 ? wsum[wid - 1] : 0);
    int total = s_total;
    if (threadIdx.x == 0) {
        if (b == 0) {
            atomicExch(&g_scanstate[0], FLAG_INC | (u32)total);
            s_prefix = 0;
        } else {
            atomicExch(&g_scanstate[b], FLAG_AGG | (u32)total);
            int pref = 0;
            int j = b - 1;
            while (j >= 0) {
                u32 st;
                do { st = atomicAdd(&g_scanstate[j], 0u); } while ((st & 0xC0000000u) == 0u);
                pref += (int)(st & VALMASK);
                if (st & FLAG_INC) break;
                j--;
            }
            atomicExch(&g_scanstate[b], FLAG_INC | (u32)(pref + total));
            s_prefix = pref;
        }
    }
    __syncthreads();
    int off = s_prefix;
    if (i < n) {
        int r = incl - v + off;
        g_rowstart[i] = r;
        g_cursor[i] = r;
    }
    if (b == nb - 1 && threadIdx.x == 0)
        g_rowstart[n] = off + total;
}

// ---------------- fill: reads edge_index directly (inline dtype vote) ----------------
__global__ void fill_kernel(const int* __restrict__ ei, int E, int n) {
    __shared__ int s_nz;
    if (threadIdx.x == 0) s_nz = 0;
    __syncthreads();
    if (((const unsigned*)ei)[2 * threadIdx.x + 1] != 0u) atomicAdd(&s_nz, 1);
    __syncthreads();
    bool is64 = (s_nz == 0);
    int e = blockIdx.x * 256 + threadIdx.x;
    if (e >= E) return;
    int s, d;
    if (is64) {
        const long long* p = (const long long*)ei;
        s = (int)p[e];
        d = (int)p[(size_t)E + e];
    } else {
        s = ei[e];
        d = ei[E + e];
    }
    if ((unsigned)s >= (unsigned)n) s = 0;
    if ((unsigned)d >= (unsigned)n) d = 0;
    int pos = atomicAdd(&g_cursor[d], 1);
    g_csr[pos] = s;
}

// ---------------- layer-1 aggregation: warp per node + g_pq zeroing ----------------
__global__ void agg1_kernel(int n) {
    int w = (blockIdx.x * blockDim.x + threadIdx.x) >> 5;
    int lane = threadIdx.x & 31;
    if (w >= n) return;
    if (lane == 0)
        *(float4*)&g_pq[w * 4] = make_float4(0.f, 0.f, 0.f, 0.f);
    int s0 = g_rowstart[w], s1 = g_rowstart[w + 1];
    float f0 = 0.f, f1 = 0.f, f2 = 0.f, f3 = 0.f;
    float f4 = 0.f, f5 = 0.f, f6 = 0.f, f7 = 0.f;
    int e = s0;
    uint4 v = make_uint4(0, 0, 0, 0);
    if (e < s1) v = *(const uint4*)(g_xhalf + (size_t)g_csr[e] * C + 8 * lane);
    while (e < s1) {
        uint4 cur = v;
        if (e + 1 < s1) v = *(const uint4*)(g_xhalf + (size_t)g_csr[e + 1] * C + 8 * lane);
        float2 p0 = __half22float2(*(__half2*)&cur.x);
        float2 p1 = __half22float2(*(__half2*)&cur.y);
        float2 p2 = __half22float2(*(__half2*)&cur.z);
        float2 p3 = __half22float2(*(__half2*)&cur.w);
        f0 += p0.x; f1 += p0.y; f2 += p1.x; f3 += p1.y;
        f4 += p2.x; f5 += p2.y; f6 += p3.x; f7 += p3.y;
        e++;
    }
    float inv = (s1 > s0) ? 1.f / (float)(s1 - s0) : 0.f;
    f0 *= inv; f1 *= inv; f2 *= inv; f3 *= inv;
    f4 *= inv; f5 *= inv; f6 *= inv; f7 *= inv;
    *(uint4*)(g_agghalf + (size_t)w * C + 8 * lane) =
        make_uint4(packhf(f0, f1), packhf(f2, f3), packhf(f4, f5), packhf(f6, f7));
}

// ---------------- fp16 mma GEMM: 128x128 tiles, 256 thr, 2 CTA/SM, fused pq ----------
// Grid (mtiles, 2): blockIdx.y = column half (128 cols of 256).
// D = A * W (fp16), fp32 accum. K=512, 16 tiles of 32. 2-stage cp.async.
// pq partials accumulated via atomicAdd into g_pq (zeroed by agg1).
#define PA 40                        // smem pitch in halfs (80 bytes)
#define SA 0                         // 128*80 = 10240
#define SB 10240                     // 128*80 = 10240
#define STAGE 20480                  // x2 = 40960
#define SW2   40960                  // 128*16 = 2048
#define SB1   43008                  // 128*4  = 512
#define SMEMT 43520

__global__ void __launch_bounds__(256, 2) gemm_mma_kernel(
    const float* __restrict__ b1, const float* __restrict__ b2, int M)
{
    extern __shared__ __align__(16) char smem[];
    u32 sb = smem_u32(smem);
    int tid = threadIdx.x;
    int lane = tid & 31, wid = tid >> 5;
    int wm = wid >> 1, wn = wid & 1;          // 4m x 2n warps, warp tile 32x64
    int m0 = blockIdx.x * 128;
    int n0 = blockIdx.y * 128;

    float4* s_w2 = (float4*)(smem + SW2);
    float*  s_b1 = (float*)(smem + SB1);
    if (tid < 128) {
        s_w2[tid] = g_W2pack[n0 + tid];
        s_b1[tid] = b1[n0 + tid];
    }

    // cp.async: A 512 x 16B chunks, B 512 x 16B chunks; 2 A + 2 B per thread
    int arow = tid >> 1, ach = tid & 1;       // ach covers 32B (2 chunks)
    int am = m0 + arow;
    u32 asz = (am < M) ? 16u : 0u;
    u32 a_soff = (u32)(arow * 80 + ach * 32);
    size_t a_goff = (size_t)am * C + ach * 16;
    u32 b_soff = a_soff;
    size_t b_goff = (size_t)(n0 + arow) * 512 + ach * 16;

    auto issue = [&](int kt, int st) {
        u32 s0 = sb + st * STAGE;
        const __half* asrc = (kt < 8) ? g_agghalf : g_xhalf;
        size_t ago = a_goff + (size_t)(kt & 7) * 32;
        CP16(s0 + SA + a_soff, asrc + ago, asz);
        CP16(s0 + SA + a_soff + 16, asrc + ago + 8, asz);
        size_t bgo = b_goff + (size_t)kt * 32;
        CP16(s0 + SB + b_soff, g_Whalf + bgo, 16u);
        CP16(s0 + SB + b_soff + 16, g_Whalf + bgo + 8, 16u);
        CP_COMMIT();
    };

    float c[2][8][4];
    #pragma unroll
    for (int mi = 0; mi < 2; mi++)
        #pragma unroll
        for (int ni = 0; ni < 8; ni++)
            #pragma unroll
            for (int j = 0; j < 4; j++) c[mi][ni][j] = 0.f;

    // ldmatrix lane offsets (bytes)
    u32 aoff = (u32)(((((lane >> 3) & 1) * 8) + (lane & 7)) * 80 + (lane >> 4) * 16);
    u32 boff = (u32)(((((lane >> 4) & 1) * 8) + (lane & 7)) * 80 + ((lane >> 3) & 1) * 16);
    u32 a_base0 = (u32)((32 * wm) * 80) + aoff;
    u32 b_base0 = (u32)((64 * wn) * 80) + boff;

    int ra = lane >> 2;
    int ka2 = (lane & 3) * 2;

    issue(0, 0);
    for (int kt = 0; kt < 16; kt++) {
        if (kt < 15) { issue(kt + 1, (kt + 1) & 1); CP_WAIT(1); }
        else         { CP_WAIT(0); }
        __syncthreads();
        u32 sS = sb + (kt & 1) * STAGE;
        #pragma unroll
        for (int k16 = 0; k16 < 2; k16++) {
            u32 kb = k16 * 32;
            u32 a[2][4];
            ldsm_x4(a[0][0], a[0][1], a[0][2], a[0][3], sS + SA + a_base0 + kb);
            ldsm_x4(a[1][0], a[1][1], a[1][2], a[1][3], sS + SA + a_base0 + 16 * 80 + kb);
            u32 bh[8][2];
            #pragma unroll
            for (int n2 = 0; n2 < 4; n2++) {
                ldsm_x4(bh[2 * n2][0], bh[2 * n2][1], bh[2 * n2 + 1][0], bh[2 * n2 + 1][1],
                        sS + SB + b_base0 + (u32)(16 * n2 * 80) + kb);
            }
            #pragma unroll
            for (int mi = 0; mi < 2; mi++)
                #pragma unroll
                for (int ni = 0; ni < 8; ni++)
                    mma16816(c[mi][ni], a[mi], bh[ni]);
        }
        __syncthreads();
    }

    // ---- epilogue: h = relu(acc + b1); partial pq over this CTA's 128 cols ----
    float pp[2][2][4];
    #pragma unroll
    for (int mi = 0; mi < 2; mi++)
        #pragma unroll
        for (int hh = 0; hh < 2; hh++)
            #pragma unroll
            for (int r = 0; r < 4; r++) pp[mi][hh][r] = 0.f;
    #pragma unroll
    for (int mi = 0; mi < 2; mi++)
        #pragma unroll
        for (int ni = 0; ni < 8; ni++)
            #pragma unroll
            for (int j = 0; j < 4; j++) {
                int col = 64 * wn + 8 * ni + ka2 + (j & 1);
                float h = fmaxf(c[mi][ni][j] + s_b1[col], 0.f);
                float4 wv = s_w2[col];
                int hh = j >> 1;
                pp[mi][hh][0] = fmaf(h, wv.x, pp[mi][hh][0]);
                pp[mi][hh][1] = fmaf(h, wv.y, pp[mi][hh][1]);
                pp[mi][hh][2] = fmaf(h, wv.z, pp[mi][hh][2]);
                pp[mi][hh][3] = fmaf(h, wv.w, pp[mi][hh][3]);
            }
    #pragma unroll
    for (int mi = 0; mi < 2; mi++)
        #pragma unroll
        for (int hh = 0; hh < 2; hh++)
            #pragma unroll
            for (int r = 0; r < 4; r++) {
                float v = pp[mi][hh][r];
                v += __shfl_xor_sync(0xffffffffu, v, 1);
                v += __shfl_xor_sync(0xffffffffu, v, 2);
                pp[mi][hh][r] = v;
            }
    float* s_part = (float*)smem;   // [2 wn][128 row][4]
    __syncthreads();                // all smem (stage) reads done
    if ((lane & 3) == 0) {
        #pragma unroll
        for (int mi = 0; mi < 2; mi++)
            #pragma unroll
            for (int hh = 0; hh < 2; hh++) {
                int row = 32 * wm + 16 * mi + 8 * hh + ra;
                *(float4*)&s_part[(wn * 128 + row) * 4] =
                    make_float4(pp[mi][hh][0], pp[mi][hh][1], pp[mi][hh][2], pp[mi][hh][3]);
            }
    }
    __syncthreads();
    if (tid < 128) {
        int m = m0 + tid;
        if (m < M) {
            float4 v0 = *(float4*)&s_part[tid * 4];
            float4 v1 = *(float4*)&s_part[(128 + tid) * 4];
            float q0b = (blockIdx.y == 0) ? b2[0] : 0.f;
            float q1b = (blockIdx.y == 0) ? b2[1] : 0.f;
            atomicAdd(&g_pq[m * 4 + 0], v0.x + v1.x);
            atomicAdd(&g_pq[m * 4 + 1], v0.y + v1.y);
            atomicAdd(&g_pq[m * 4 + 2], v0.z + v1.z + q0b);
            atomicAdd(&g_pq[m * 4 + 3], v0.w + v1.w + q1b);
        }
    }
}

// ---------------- layer-2 aggregation + log_softmax + state re-zero ----------------
__global__ void final_kernel(float* __restrict__ out, int n) {
    int i = blockIdx.x * blockDim.x + threadIdx.x;
    if (i >= n) return;
    g_cnt[i] = 0;
    if (i < 64) g_scanstate[i] = 0u;
    int s0 = g_rowstart[i], s1 = g_rowstart[i + 1];
    float p0 = 0.f, p1 = 0.f;
    for (int e = s0; e < s1; e++) {
        int s = g_csr[e];
        p0 += g_pq[s * 4 + 0];
        p1 += g_pq[s * 4 + 1];
    }
    float inv = (s1 > s0) ? 1.f / (float)(s1 - s0) : 0.f;
    float o0 = p0 * inv + g_pq[i * 4 + 2];
    float o1 = p1 * inv + g_pq[i * 4 + 3];
    float m = fmaxf(o0, o1);
    float l = m + log1pf(expf(fminf(o0, o1) - m));
    out[i * 2 + 0] = o0 - l;
    out[i * 2 + 1] = o1 - l;
}

// ---------------- launcher ----------------
extern "C" void kernel_launch(void* const* d_in, const int* in_sizes, int n_in,
                              void* d_out, int out_size) {
    const float* x   = (const float*)d_in[0];
    const int*   ei  = (const int*)d_in[1];
    const float* W1l = (const float*)d_in[2];
    const float* b1  = (const float*)d_in[3];
    const float* W1r = (const float*)d_in[4];
    const float* W2l = (const float*)d_in[5];
    const float* b2  = (const float*)d_in[6];
    const float* W2r = (const float*)d_in[7];
    float* out = (float*)d_out;

    int n = in_sizes[0] / C;  if (n > NMAX) n = NMAX;
    int E = in_sizes[1] / 2;  if (E > EMAX) E = EMAX;
    int nb = (n + 1023) / 1024;
    int nbx = (n * 64 + 255) / 256;
    int nbc = (E + 255) / 256;

    cudaFuncSetAttribute(gemm_mma_kernel, cudaFuncAttributeMaxDynamicSharedMemorySize,
                         SMEMT);

    prep_kernel<<<nbx + nbc + 512, 256>>>(x, ei, W1l, W1r, W2l, W2r, n, E, nbx, nbc);
    scan_kernel<<<nb, 1024>>>(n, nb);
    fill_kernel<<<(E + 255) / 256, 256>>>(ei, E, n);
    agg1_kernel<<<(n * 32 + 255) / 256, 256>>>(n);
    dim3 gg((n + 127) / 128, 2);
    gemm_mma_kernel<<<gg, 256, SMEMT>>>(b1, b2, n);
    final_kernel<<<(n + 255) / 256, 256>>>(out, n);
}

// round 15
// speedup vs baseline: 1.0771x; 1.0771x over previous
#include <cuda_runtime.h>
#include <cuda_fp16.h>
#include <math.h>

#define NMAX 50000
#define EMAX 800000
#define C 256

typedef unsigned long long u64;
typedef unsigned int u32;

// ---------------- scratch (static device globals; no allocation) ----------------
// g_cnt / g_scanstate are zero-initialized at load and re-zeroed by final_kernel.
__device__ int   g_cnt[NMAX];
__device__ u32   g_scanstate[64];
__device__ int   g_rowstart[NMAX + 1];
__device__ int   g_cursor[NMAX];
__device__ int   g_csr[EMAX];
__device__ __align__(16) float g_pq[NMAX * 4];
__device__ __align__(16) __half g_Whalf[256 * 512];        // [W1l|W1r] fp16
__device__ __align__(16) float4 g_W2pack[256];             // {W2l0,W2l1,W2r0,W2r1}[col]
__device__ __align__(16) __half g_agghalf[(size_t)NMAX * C];
__device__ __align__(16) __half g_xhalf[(size_t)NMAX * C];

__device__ __forceinline__ u32 packhf(float a, float b) {
    __half2 h = __floats2half2_rn(a, b);
    return *(u32*)&h;
}
__device__ __forceinline__ void mma16816(float* d, const u32* a, const u32* b) {
    asm volatile(
        "mma.sync.aligned.m16n8k16.row.col.f32.f16.f16.f32 "
        "{%0,%1,%2,%3}, {%4,%5,%6,%7}, {%8,%9}, {%0,%1,%2,%3};"
        : "+f"(d[0]), "+f"(d[1]), "+f"(d[2]), "+f"(d[3])
        : "r"(a[0]), "r"(a[1]), "r"(a[2]), "r"(a[3]), "r"(b[0]), "r"(b[1]));
}
__device__ __forceinline__ void ldsm_x4(u32& r0, u32& r1, u32& r2, u32& r3, u32 addr) {
    asm volatile("ldmatrix.sync.aligned.m8n8.x4.shared.b16 {%0,%1,%2,%3}, [%4];"
                 : "=r"(r0), "=r"(r1), "=r"(r2), "=r"(r3) : "r"(addr));
}
__device__ __forceinline__ u32 smem_u32(const void* p) {
    u32 a;
    asm("{ .reg .u64 t; cvta.to.shared.u64 t, %1; cvt.u32.u64 %0, t; }" : "=r"(a) : "l"(p));
    return a;
}
#define CP16(dst, src, sz) \
    asm volatile("cp.async.cg.shared.global [%0], [%1], 16, %2;" \
                 :: "r"(dst), "l"(src), "r"(sz))
#define CP_COMMIT() asm volatile("cp.async.commit_group;")
#define CP_WAIT(n)  asm volatile("cp.async.wait_group %0;" :: "n"(n))

// ---------------- merged prep: x->fp16 | edge count (inline dtype) | W->fp16 ----------
__global__ void prep_kernel(const float* __restrict__ x, const int* __restrict__ ei,
                            const float* __restrict__ W1l, const float* __restrict__ W1r,
                            const float* __restrict__ W2l, const float* __restrict__ W2r,
                            int n, int E, int nbx, int nbc) {
    int b = blockIdx.x;
    int tid = threadIdx.x;
    if (b < nbx) {
        int idx = b * 256 + tid;
        if (idx < n * 64) {
            float4 v = *(const float4*)(x + (size_t)idx * 4);
            *(uint2*)(g_xhalf + (size_t)idx * 4) =
                make_uint2(packhf(v.x, v.y), packhf(v.z, v.w));
        }
    } else if (b < nbx + nbc) {
        __shared__ int s_nz;
        if (tid == 0) s_nz = 0;
        __syncthreads();
        if (((const unsigned*)ei)[2 * tid + 1] != 0u) atomicAdd(&s_nz, 1);
        __syncthreads();
        bool is64 = (s_nz == 0);
        int e = (b - nbx) * 256 + tid;
        if (e < E) {
            int d;
            if (is64) d = (int)((const long long*)ei)[(size_t)E + e];
            else      d = ei[E + e];
            if ((unsigned)d >= (unsigned)n) d = 0;
            atomicAdd(&g_cnt[d], 1);
        }
    } else {
        int idx = (b - nbx - nbc) * 256 + tid;   // < 131072
        int nrow = idx >> 9;
        int k = idx & 511;
        float w = (k < 256) ? W1l[nrow * 256 + k] : W1r[nrow * 256 + (k - 256)];
        g_Whalf[idx] = __float2half_rn(w);
        if (idx < 256)
            g_W2pack[idx] = make_float4(W2l[idx], W2l[256 + idx], W2r[idx], W2r[256 + idx]);
    }
}

// ---------------- single-kernel exclusive scan (decoupled lookback, nb<=49 blocks) ----
#define FLAG_AGG 0x40000000u
#define FLAG_INC 0x80000000u
#define VALMASK  0x0FFFFFFFu

__global__ void scan_kernel(int n, int nb) {
    int b = blockIdx.x;
    int i = b * 1024 + threadIdx.x;
    int v = (i < n) ? g_cnt[i] : 0;
    int lane = threadIdx.x & 31, wid = threadIdx.x >> 5;
    int x = v;
    #pragma unroll
    for (int off = 1; off < 32; off <<= 1) {
        int t = __shfl_up_sync(0xffffffffu, x, off);
        if (lane >= off) x += t;
    }
    __shared__ int wsum[32];
    __shared__ int s_prefix, s_total;
    if (lane == 31) wsum[wid] = x;
    __syncthreads();
    if (wid == 0) {
        int s = wsum[lane];
        #pragma unroll
        for (int off = 1; off < 32; off <<= 1) {
            int t = __shfl_up_sync(0xffffffffu, s, off);
            if (lane >= off) s += t;
        }
        wsum[lane] = s;
        if (lane == 31) s_total = s;
    }
    __syncthreads();
    int incl = x + (wid > 0 ? wsum[wid - 1] : 0);
    int total = s_total;
    if (threadIdx.x == 0) {
        if (b == 0) {
            atomicExch(&g_scanstate[0], FLAG_INC | (u32)total);
            s_prefix = 0;
        } else {
            atomicExch(&g_scanstate[b], FLAG_AGG | (u32)total);
            int pref = 0;
            int j = b - 1;
            while (j >= 0) {
                u32 st;
                do { st = atomicAdd(&g_scanstate[j], 0u); } while ((st & 0xC0000000u) == 0u);
                pref += (int)(st & VALMASK);
                if (st & FLAG_INC) break;
                j--;
            }
            atomicExch(&g_scanstate[b], FLAG_INC | (u32)(pref + total));
            s_prefix = pref;
        }
    }
    __syncthreads();
    int off = s_prefix;
    if (i < n) {
        int r = incl - v + off;
        g_rowstart[i] = r;
        g_cursor[i] = r;
    }
    if (b == nb - 1 && threadIdx.x == 0)
        g_rowstart[n] = off + total;
}

// ---------------- fill: reads edge_index directly (inline dtype vote) ----------------
__global__ void fill_kernel(const int* __restrict__ ei, int E, int n) {
    __shared__ int s_nz;
    if (threadIdx.x == 0) s_nz = 0;
    __syncthreads();
    if (((const unsigned*)ei)[2 * threadIdx.x + 1] != 0u) atomicAdd(&s_nz, 1);
    __syncthreads();
    bool is64 = (s_nz == 0);
    int e = blockIdx.x * 256 + threadIdx.x;
    if (e >= E) return;
    int s, d;
    if (is64) {
        const long long* p = (const long long*)ei;
        s = (int)p[e];
        d = (int)p[(size_t)E + e];
    } else {
        s = ei[e];
        d = ei[E + e];
    }
    if ((unsigned)s >= (unsigned)n) s = 0;
    if ((unsigned)d >= (unsigned)n) d = 0;
    int pos = atomicAdd(&g_cursor[d], 1);
    g_csr[pos] = s;
}

// ---------------- layer-1 aggregation: warp per node, depth-2 pipelined gather ----------
__global__ void agg1_kernel(int n) {
    int w = (blockIdx.x * blockDim.x + threadIdx.x) >> 5;
    int lane = threadIdx.x & 31;
    if (w >= n) return;
    int s0 = g_rowstart[w], s1 = g_rowstart[w + 1];
    float f0 = 0.f, f1 = 0.f, f2 = 0.f, f3 = 0.f;
    float f4 = 0.f, f5 = 0.f, f6 = 0.f, f7 = 0.f;
    int e = s0;
    uint4 v = make_uint4(0, 0, 0, 0);
    if (e < s1) v = *(const uint4*)(g_xhalf + (size_t)g_csr[e] * C + 8 * lane);
    while (e < s1) {
        uint4 cur = v;
        if (e + 1 < s1) v = *(const uint4*)(g_xhalf + (size_t)g_csr[e + 1] * C + 8 * lane);
        float2 p0 = __half22float2(*(__half2*)&cur.x);
        float2 p1 = __half22float2(*(__half2*)&cur.y);
        float2 p2 = __half22float2(*(__half2*)&cur.z);
        float2 p3 = __half22float2(*(__half2*)&cur.w);
        f0 += p0.x; f1 += p0.y; f2 += p1.x; f3 += p1.y;
        f4 += p2.x; f5 += p2.y; f6 += p3.x; f7 += p3.y;
        e++;
    }
    float inv = (s1 > s0) ? 1.f / (float)(s1 - s0) : 0.f;
    f0 *= inv; f1 *= inv; f2 *= inv; f3 *= inv;
    f4 *= inv; f5 *= inv; f6 *= inv; f7 *= inv;
    *(uint4*)(g_agghalf + (size_t)w * C + 8 * lane) =
        make_uint4(packhf(f0, f1), packhf(f2, f3), packhf(f4, f5), packhf(f6, f7));
}

// ---------------- 3-stage fp16 mma GEMM (ldmatrix frags, 1 sync/kt) + fused pq --------
// CTA: 128 rows x 256 cols, 512 threads, warp grid 4m x 4n, warp tile 32x64.
// D = A * W (both fp16), fp32 accum. K=512, 16 tiles of 32. 3-stage cp.async.
#define PA 40                        // smem pitch in halfs (80 bytes)
#define SA 0                         // 128*80 = 10240
#define SB 10240                     // 256*80 = 20480
#define STAGE 30720                  // x3 = 92160
#define SW2   92160                  // 256*16 = 4096
#define SB1   96256                  // 1024
#define SMEMT 97280

__global__ void __launch_bounds__(512, 1) gemm_mma_kernel(
    const float* __restrict__ b1, const float* __restrict__ b2, int M)
{
    extern __shared__ __align__(16) char smem[];
    u32 sb = smem_u32(smem);
    int tid = threadIdx.x;
    int lane = tid & 31, wid = tid >> 5;
    int wm = wid >> 2, wn = wid & 3;
    int m0 = blockIdx.x * 128;

    float4* s_w2 = (float4*)(smem + SW2);
    float*  s_b1 = (float*)(smem + SB1);
    if (tid < 256) {
        s_w2[tid] = g_W2pack[tid];
        s_b1[tid] = b1[tid];
    }

    int arow = tid >> 2, ach = tid & 3;
    int am = m0 + arow;
    u32 asz = (am < M) ? 16u : 0u;
    u32 a_soff = (u32)(arow * 80 + ach * 16);
    size_t a_goff = (size_t)am * C + ach * 8;

    auto issue = [&](int kt, int st) {
        u32 s0 = sb + st * STAGE;
        const __half* asrc = (kt < 8) ? g_agghalf : g_xhalf;
        size_t ago = a_goff + (size_t)(kt & 7) * 32;
        CP16(s0 + SA + a_soff, asrc + ago, asz);
        int kg = kt * 32;
        #pragma unroll
        for (int i = 0; i < 2; i++) {
            int t = tid + i * 512;
            int nr = t >> 2, ch = t & 3;
            CP16(s0 + SB + (u32)(nr * 80 + ch * 16),
                 g_Whalf + (size_t)nr * 512 + kg + ch * 8, 16u);
        }
        CP_COMMIT();
    };

    float c[2][8][4];
    #pragma unroll
    for (int mi = 0; mi < 2; mi++)
        #pragma unroll
        for (int ni = 0; ni < 8; ni++)
            #pragma unroll
            for (int j = 0; j < 4; j++) c[mi][ni][j] = 0.f;

    // ldmatrix lane-dependent offsets (bytes)
    u32 aoff = (u32)(((((lane >> 3) & 1) * 8) + (lane & 7)) * 80 + (lane >> 4) * 16);
    u32 boff = (u32)(((((lane >> 4) & 1) * 8) + (lane & 7)) * 80 + ((lane >> 3) & 1) * 16);
    u32 a_base0 = (u32)((32 * wm) * 80) + aoff;
    u32 b_base0 = (u32)((64 * wn) * 80) + boff;

    int ra = lane >> 2;
    int ka2 = (lane & 3) * 2;

    issue(0, 0);
    issue(1, 1);
    int st = 0;
    for (int kt = 0; kt < 16; kt++) {
        if (kt < 15) CP_WAIT(1);     // tile kt complete (kt+1 may remain in flight)
        else         CP_WAIT(0);
        __syncthreads();             // publish tile kt; all reads of stage (kt-1)%3 done
        if (kt < 14) issue(kt + 2, (st + 2 >= 3) ? (st - 1) : (st + 2));
        u32 sS = sb + st * STAGE;
        #pragma unroll
        for (int k16 = 0; k16 < 2; k16++) {
            u32 kb = k16 * 32;
            u32 a[2][4];
            ldsm_x4(a[0][0], a[0][1], a[0][2], a[0][3], sS + SA + a_base0 + kb);
            ldsm_x4(a[1][0], a[1][1], a[1][2], a[1][3], sS + SA + a_base0 + 16 * 80 + kb);
            u32 bh[8][2];
            #pragma unroll
            for (int n2 = 0; n2 < 4; n2++) {
                ldsm_x4(bh[2 * n2][0], bh[2 * n2][1], bh[2 * n2 + 1][0], bh[2 * n2 + 1][1],
                        sS + SB + b_base0 + (u32)(16 * n2 * 80) + kb);
            }
            #pragma unroll
            for (int mi = 0; mi < 2; mi++)
                #pragma unroll
                for (int ni = 0; ni < 8; ni++)
                    mma16816(c[mi][ni], a[mi], bh[ni]);
        }
        st = (st == 2) ? 0 : (st + 1);
    }
    __syncthreads();   // all stage reads done before s_part overwrites smem

    // ---- epilogue: h = relu(acc + b1); fused p,q projection
    float pp[2][2][4];
    #pragma unroll
    for (int mi = 0; mi < 2; mi++)
        #pragma unroll
        for (int hh = 0; hh < 2; hh++)
            #pragma unroll
            for (int r = 0; r < 4; r++) pp[mi][hh][r] = 0.f;
    #pragma unroll
    for (int mi = 0; mi < 2; mi++)
        #pragma unroll
        for (int ni = 0; ni < 8; ni++)
            #pragma unroll
            for (int j = 0; j < 4; j++) {
                int col = 64 * wn + 8 * ni + ka2 + (j & 1);
                float h = fmaxf(c[mi][ni][j] + s_b1[col], 0.f);
                float4 wv = s_w2[col];
                int hh = j >> 1;
                pp[mi][hh][0] = fmaf(h, wv.x, pp[mi][hh][0]);
                pp[mi][hh][1] = fmaf(h, wv.y, pp[mi][hh][1]);
                pp[mi][hh][2] = fmaf(h, wv.z, pp[mi][hh][2]);
                pp[mi][hh][3] = fmaf(h, wv.w, pp[mi][hh][3]);
            }
    #pragma unroll
    for (int mi = 0; mi < 2; mi++)
        #pragma unroll
        for (int hh = 0; hh < 2; hh++)
            #pragma unroll
            for (int r = 0; r < 4; r++) {
                float v = pp[mi][hh][r];
                v += __shfl_xor_sync(0xffffffffu, v, 1);
                v += __shfl_xor_sync(0xffffffffu, v, 2);
                pp[mi][hh][r] = v;
            }
    float* s_part = (float*)smem;   // [4 wn][128 row][4]
    if ((lane & 3) == 0) {
        #pragma unroll
        for (int mi = 0; mi < 2; mi++)
            #pragma unroll
            for (int hh = 0; hh < 2; hh++) {
                int row = 32 * wm + 16 * mi + 8 * hh + ra;
                *(float4*)&s_part[(wn * 128 + row) * 4] =
                    make_float4(pp[mi][hh][0], pp[mi][hh][1], pp[mi][hh][2], pp[mi][hh][3]);
            }
    }
    __syncthreads();
    if (tid < 128) {
        int m = m0 + tid;
        if (m < M) {
            float4 s = make_float4(0.f, 0.f, 0.f, 0.f);
            #pragma unroll
            for (int w = 0; w < 4; w++) {
                float4 v = *(float4*)&s_part[(w * 128 + tid) * 4];
                s.x += v.x; s.y += v.y; s.z += v.z; s.w += v.w;
            }
            *(float4*)&g_pq[m * 4] = make_float4(s.x, s.y, s.z + b2[0], s.w + b2[1]);
        }
    }
}

// ---------------- layer-2 aggregation + log_softmax + state re-zero ----------------
__global__ void final_kernel(float* __restrict__ out, int n) {
    int i = blockIdx.x * blockDim.x + threadIdx.x;
    if (i >= n) return;
    g_cnt[i] = 0;
    if (i < 64) g_scanstate[i] = 0u;
    int s0 = g_rowstart[i], s1 = g_rowstart[i + 1];
    float p0 = 0.f, p1 = 0.f;
    for (int e = s0; e < s1; e++) {
        int s = g_csr[e];
        p0 += g_pq[s * 4 + 0];
        p1 += g_pq[s * 4 + 1];
    }
    float inv = (s1 > s0) ? 1.f / (float)(s1 - s0) : 0.f;
    float o0 = p0 * inv + g_pq[i * 4 + 2];
    float o1 = p1 * inv + g_pq[i * 4 + 3];
    float m = fmaxf(o0, o1);
    float l = m + log1pf(expf(fminf(o0, o1) - m));
    out[i * 2 + 0] = o0 - l;
    out[i * 2 + 1] = o1 - l;
}

// ---------------- launcher ----------------
extern "C" void kernel_launch(void* const* d_in, const int* in_sizes, int n_in,
                              void* d_out, int out_size) {
    const float* x   = (const float*)d_in[0];
    const int*   ei  = (const int*)d_in[1];
    const float* W1l = (const float*)d_in[2];
    const float* b1  = (const float*)d_in[3];
    const float* W1r = (const float*)d_in[4];
    const float* W2l = (const float*)d_in[5];
    const float* b2  = (const float*)d_in[6];
    const float* W2r = (const float*)d_in[7];
    float* out = (float*)d_out;

    int n = in_sizes[0] / C;  if (n > NMAX) n = NMAX;
    int E = in_sizes[1] / 2;  if (E > EMAX) E = EMAX;
    int nb = (n + 1023) / 1024;
    int nbx = (n * 64 + 255) / 256;
    int nbc = (E + 255) / 256;

    cudaFuncSetAttribute(gemm_mma_kernel, cudaFuncAttributeMaxDynamicSharedMemorySize,
                         SMEMT);

    prep_kernel<<<nbx + nbc + 512, 256>>>(x, ei, W1l, W1r, W2l, W2r, n, E, nbx, nbc);
    scan_kernel<<<nb, 1024>>>(n, nb);
    fill_kernel<<<(E + 255) / 256, 256>>>(ei, E, n);
    agg1_kernel<<<(n * 32 + 255) / 256, 256>>>(n);
    gemm_mma_kernel<<<(n + 127) / 128, 512, SMEMT>>>(b1, b2, n);
    final_kernel<<<(n + 255) / 256, 256>>>(out, n);
}